// round 4
// baseline (speedup 1.0000x reference)
#include <cuda_runtime.h>

#define NMAX 100000
#define EMAX 1000000
#define LMAX 200000

// ---------------------------------------------------------------------------
// Static device scratch (allocation-free)
// ---------------------------------------------------------------------------
__device__ int    g_deg[NMAX];
__device__ float  g_dinv[NMAX];
__device__ int    g_off[NMAX];               // partial CSR offsets (block-local scan)
__device__ int    g_cur[NMAX];               // fill cursors
__device__ int    g_bsum[256];               // scan block sums (exclusive after scan2)
__device__ int    g_csr[EMAX];               // CSR: src node per slot
__device__ float4 g_h[(size_t)NMAX * 32];    // h = x@W (unscaled)
__device__ float4 g_x[(size_t)NMAX * 32];    // layer output
__device__ int    g_eidx[2 * EMAX];          // decoded src|dst
__device__ int    g_lidx[2 * LMAX];          // decoded label endpoints
__device__ int    g_is64;

// ---------------------------------------------------------------------------
// f32x2 packed-FMA helpers (sm_103a dual-rate fp32 path)
// ---------------------------------------------------------------------------
__device__ __forceinline__ unsigned long long fma2(unsigned long long a,
                                                   unsigned long long b,
                                                   unsigned long long c) {
    unsigned long long d;
    asm("fma.rn.f32x2 %0, %1, %2, %3;" : "=l"(d) : "l"(a), "l"(b), "l"(c));
    return d;
}
__device__ __forceinline__ unsigned long long pack2(float lo, float hi) {
    unsigned long long o;
    asm("mov.b64 %0, {%1, %2};" : "=l"(o) : "f"(lo), "f"(hi));
    return o;
}
__device__ __forceinline__ void unpack2(unsigned long long v, float& lo, float& hi) {
    asm("mov.b64 {%0, %1}, %2;" : "=f"(lo), "=f"(hi) : "l"(v));
}

// ---------------------------------------------------------------------------
// init: dtype sniff (thread 0) + zero deg/cur (all threads)
// ---------------------------------------------------------------------------
__global__ void k_init(const unsigned* __restrict__ w, int n) {
    int i = blockIdx.x * blockDim.x + threadIdx.x;
    if (i == 0) {
        int is64 = 1;
        for (int j = 0; j < 32; j++)
            if (w[2 * j + 1] != 0u) { is64 = 0; break; }
        g_is64 = is64;
    }
    if (i < n) { g_deg[i] = 0; g_cur[i] = 0; }
}

__global__ void k_cvt_lbl(const void* __restrict__ raw, int count, int n) {
    int i = blockIdx.x * blockDim.x + threadIdx.x;
    if (i >= count) return;
    long long v = g_is64 ? ((const long long*)raw)[i]
                         : (long long)((const int*)raw)[i];
    int x = (int)v;
    x = x < 0 ? 0 : (x >= n ? n - 1 : x);
    g_lidx[i] = x;
}

// decode edges + histogram dst degrees in the same pass
__global__ void k_cvt_edges(const void* __restrict__ raw, int twoE, int E, int n) {
    int i = blockIdx.x * blockDim.x + threadIdx.x;
    if (i >= twoE) return;
    long long v = g_is64 ? ((const long long*)raw)[i]
                         : (long long)((const int*)raw)[i];
    int x = (int)v;
    x = x < 0 ? 0 : (x >= n ? n - 1 : x);
    g_eidx[i] = x;
    if (i >= E) atomicAdd(&g_deg[x], 1);   // dst half
}

// ---------------------------------------------------------------------------
// scan of deg -> off (block-local exclusive; bsum added downstream)
// scan1 also computes dinv = rsqrt(deg+1)
// ---------------------------------------------------------------------------
__global__ void k_scan1(int n) {
    __shared__ int s[512];
    int t = threadIdx.x;
    int i = blockIdx.x * 512 + t;
    int v = (i < n) ? g_deg[i] : 0;
    if (i < n) g_dinv[i] = rsqrtf((float)v + 1.0f);
    s[t] = v;
    __syncthreads();
    for (int off = 1; off < 512; off <<= 1) {
        int add = (t >= off) ? s[t - off] : 0;
        __syncthreads();
        s[t] += add;
        __syncthreads();
    }
    if (i < n) g_off[i] = s[t] - v;          // block-local exclusive
    if (t == 511) g_bsum[blockIdx.x] = s[511];
}

__global__ void k_scan2(int nb) {
    __shared__ int s[256];
    int t = threadIdx.x;
    int v = (t < nb) ? g_bsum[t] : 0;
    s[t] = v;
    __syncthreads();
    for (int off = 1; off < 256; off <<= 1) {
        int add = (t >= off) ? s[t - off] : 0;
        __syncthreads();
        s[t] += add;
        __syncthreads();
    }
    if (t < nb) g_bsum[t] = s[t] - v;        // exclusive block sums
}

__global__ void k_fill(int E) {
    int i = blockIdx.x * blockDim.x + threadIdx.x;
    if (i >= E) return;
    int s = g_eidx[i];
    int d = g_eidx[E + i];
    int pos = g_off[d] + g_bsum[d >> 9] + atomicAdd(&g_cur[d], 1);
    g_csr[pos] = s;
}

// ---------------------------------------------------------------------------
// GEMM: g_h[row] = X[row] @ W  (unscaled; dinv applied in k_agg)
// BM=128, BN=128(full), BK=32; 256 threads; 8x8/thread via f32x2
// ---------------------------------------------------------------------------
__global__ void __launch_bounds__(256)
k_gemm(const float* __restrict__ Xext, const float* __restrict__ W,
       int n, int use_internal) {
    const float* X = use_internal ? (const float*)g_x : Xext;

    __shared__ float As[32][132];   // [k][row], padded
    __shared__ float Ws[32][132];   // [k][col], padded

    int tid = threadIdx.x;
    int tx = tid & 15;              // col group: cols tx*8 .. tx*8+7
    int ty = tid >> 4;              // row group: rows ty*8 .. ty*8+7
    int rowBase = blockIdx.x * 128;

    unsigned long long acc[8][4];
#pragma unroll
    for (int m = 0; m < 8; m++)
#pragma unroll
        for (int c = 0; c < 4; c++) acc[m][c] = 0ull;

    for (int kk = 0; kk < 128; kk += 32) {
#pragma unroll
        for (int i = 0; i < 4; i++) {
            int fi = tid + i * 256;
            int r = fi >> 3;
            int q = fi & 7;
            int row = rowBase + r;
            float4 v = make_float4(0.f, 0.f, 0.f, 0.f);
            if (row < n)
                v = *(const float4*)(X + (size_t)row * 128 + kk + q * 4);
            As[q * 4 + 0][r] = v.x;
            As[q * 4 + 1][r] = v.y;
            As[q * 4 + 2][r] = v.z;
            As[q * 4 + 3][r] = v.w;
        }
#pragma unroll
        for (int i = 0; i < 4; i++) {
            int fi = tid + i * 256;
            int k = fi >> 5;
            int q = fi & 31;
            float4 v = *(const float4*)(W + (size_t)(kk + k) * 128 + q * 4);
            *(float4*)&Ws[k][q * 4] = v;
        }
        __syncthreads();

#pragma unroll
        for (int k = 0; k < 32; k++) {
            float4 a0 = *(const float4*)&As[k][ty * 8];
            float4 a1 = *(const float4*)&As[k][ty * 8 + 4];
            unsigned long long ap[8];
            ap[0] = pack2(a0.x, a0.x); ap[1] = pack2(a0.y, a0.y);
            ap[2] = pack2(a0.z, a0.z); ap[3] = pack2(a0.w, a0.w);
            ap[4] = pack2(a1.x, a1.x); ap[5] = pack2(a1.y, a1.y);
            ap[6] = pack2(a1.z, a1.z); ap[7] = pack2(a1.w, a1.w);
            const unsigned long long* wp =
                (const unsigned long long*)&Ws[k][tx * 8];
            unsigned long long w0 = wp[0], w1 = wp[1], w2 = wp[2], w3 = wp[3];
#pragma unroll
            for (int m = 0; m < 8; m++) {
                acc[m][0] = fma2(ap[m], w0, acc[m][0]);
                acc[m][1] = fma2(ap[m], w1, acc[m][1]);
                acc[m][2] = fma2(ap[m], w2, acc[m][2]);
                acc[m][3] = fma2(ap[m], w3, acc[m][3]);
            }
        }
        __syncthreads();
    }

#pragma unroll
    for (int m = 0; m < 8; m++) {
        int row = rowBase + ty * 8 + m;
        if (row < n) {
            float4 v0, v1;
            unpack2(acc[m][0], v0.x, v0.y);
            unpack2(acc[m][1], v0.z, v0.w);
            unpack2(acc[m][2], v1.x, v1.y);
            unpack2(acc[m][3], v1.z, v1.w);
            g_h[(size_t)row * 32 + tx * 2 + 0] = v0;
            g_h[(size_t)row * 32 + tx * 2 + 1] = v1;
        }
    }
}

// ---------------------------------------------------------------------------
// CSR pull aggregation + fused finalize:
// x[d] = act( dinv[d] * ( dinv[d]*h[d] + sum_s dinv[s]*h[s] ) + b )
// one warp per node, lane = float4 slice
// ---------------------------------------------------------------------------
__global__ void k_agg(const float* __restrict__ bias, int n, int do_relu) {
    int gw = (blockIdx.x * blockDim.x + threadIdx.x) >> 5;
    int lane = threadIdx.x & 31;
    if (gw >= n) return;
    int d = gw;

    float wd = g_dinv[d];
    float4 hd = g_h[(size_t)d * 32 + lane];
    float4 acc = make_float4(wd * hd.x, wd * hd.y, wd * hd.z, wd * hd.w);

    int o = g_off[d] + g_bsum[d >> 9];
    int c = g_deg[d];

    int j = 0;
    for (; j + 4 <= c; j += 4) {
        int s0 = g_csr[o + j + 0];
        int s1 = g_csr[o + j + 1];
        int s2 = g_csr[o + j + 2];
        int s3 = g_csr[o + j + 3];
        float w0 = g_dinv[s0], w1 = g_dinv[s1], w2 = g_dinv[s2], w3 = g_dinv[s3];
        float4 v0 = g_h[(size_t)s0 * 32 + lane];
        float4 v1 = g_h[(size_t)s1 * 32 + lane];
        float4 v2 = g_h[(size_t)s2 * 32 + lane];
        float4 v3 = g_h[(size_t)s3 * 32 + lane];
        acc.x = fmaf(w0, v0.x, fmaf(w1, v1.x, fmaf(w2, v2.x, fmaf(w3, v3.x, acc.x))));
        acc.y = fmaf(w0, v0.y, fmaf(w1, v1.y, fmaf(w2, v2.y, fmaf(w3, v3.y, acc.y))));
        acc.z = fmaf(w0, v0.z, fmaf(w1, v1.z, fmaf(w2, v2.z, fmaf(w3, v3.z, acc.z))));
        acc.w = fmaf(w0, v0.w, fmaf(w1, v1.w, fmaf(w2, v2.w, fmaf(w3, v3.w, acc.w))));
    }
    for (; j < c; j++) {
        int s = g_csr[o + j];
        float ws = g_dinv[s];
        float4 v = g_h[(size_t)s * 32 + lane];
        acc.x = fmaf(ws, v.x, acc.x);
        acc.y = fmaf(ws, v.y, acc.y);
        acc.z = fmaf(ws, v.z, acc.z);
        acc.w = fmaf(ws, v.w, acc.w);
    }

    float4 bv = ((const float4*)bias)[lane];
    float4 r = make_float4(fmaf(wd, acc.x, bv.x), fmaf(wd, acc.y, bv.y),
                           fmaf(wd, acc.z, bv.z), fmaf(wd, acc.w, bv.w));
    if (do_relu) {
        r.x = fmaxf(r.x, 0.f); r.y = fmaxf(r.y, 0.f);
        r.z = fmaxf(r.z, 0.f); r.w = fmaxf(r.w, 0.f);
    }
    g_x[(size_t)d * 32 + lane] = r;
}

// ---------------------------------------------------------------------------
// edge scoring: one warp per label edge, dot over 128 dims
// ---------------------------------------------------------------------------
__global__ void k_score(float* __restrict__ out, int L) {
    int gw = (blockIdx.x * blockDim.x + threadIdx.x) >> 5;
    int lane = threadIdx.x & 31;
    if (gw >= L) return;
    int u = g_lidx[gw];
    int v = g_lidx[L + gw];
    float4 xu = g_x[(size_t)u * 32 + lane];
    float4 xv = g_x[(size_t)v * 32 + lane];
    float p = xu.x * xv.x + xu.y * xv.y + xu.z * xv.z + xu.w * xv.w;
#pragma unroll
    for (int off = 16; off > 0; off >>= 1)
        p += __shfl_xor_sync(0xffffffffu, p, off);
    if (lane == 0) out[gw] = p;
}

// ---------------------------------------------------------------------------
extern "C" void kernel_launch(void* const* d_in, const int* in_sizes, int n_in,
                              void* d_out, int out_size) {
    const float* X   = (const float*)d_in[0];
    const void* eidx = d_in[1];
    const void* lidx = d_in[2];
    const float* W1  = (const float*)d_in[3];
    const float* b1  = (const float*)d_in[4];
    const float* W2  = (const float*)d_in[5];
    const float* b2  = (const float*)d_in[6];

    int N = in_sizes[0] / 128;
    int E = in_sizes[1] / 2;
    int L = in_sizes[2] / 2;
    int nb1 = (N + 511) / 512;

    // One-time host objects (host-side only; device work is identical per call)
    static cudaStream_t s2 = nullptr;
    static cudaEvent_t evFork = nullptr, evJoin = nullptr;
    if (!s2) {
        cudaStreamCreateWithFlags(&s2, cudaStreamNonBlocking);
        cudaEventCreateWithFlags(&evFork, cudaEventDisableTiming);
        cudaEventCreateWithFlags(&evJoin, cudaEventDisableTiming);
    }

    // --- main stream: sniff dtype + zero, then fork ---
    k_init<<<(N + 255) / 256, 256>>>((const unsigned*)eidx, N);
    cudaEventRecord(evFork, 0);
    cudaStreamWaitEvent(s2, evFork, 0);

    // --- side stream: FMA-bound GEMM1 (independent of graph structure) ---
    k_gemm<<<(N + 127) / 128, 256, 0, s2>>>(X, W1, N, 0);
    k_cvt_lbl<<<(2 * L + 255) / 256, 256, 0, s2>>>(lidx, 2 * L, N);
    cudaEventRecord(evJoin, s2);

    // --- main stream: L2/atomic-bound CSR build, concurrent with GEMM1 ---
    k_cvt_edges<<<(2 * E + 255) / 256, 256>>>(eidx, 2 * E, E, N);
    k_scan1<<<nb1, 512>>>(N);
    k_scan2<<<1, 256>>>(nb1);
    k_fill<<<(E + 255) / 256, 256>>>(E);

    // --- join, then the serial tail ---
    cudaStreamWaitEvent(0, evJoin, 0);
    k_agg<<<(N + 7) / 8, 256>>>(b1, N, 1);
    k_gemm<<<(N + 127) / 128, 256>>>(X, W2, N, 1);
    k_agg<<<(N + 7) / 8, 256>>>(b2, N, 0);
    k_score<<<(L + 7) / 8, 256>>>((float*)d_out, L);
}